// round 2
// baseline (speedup 1.0000x reference)
#include <cuda_runtime.h>
#include <math.h>

#define NMAX 50000
#define EMAX 800000
#define DIM 128
#define KPAD 192   // 128 emb + 34 fixed = 162, padded to 192

// ---------------- scratch (device globals; no allocation allowed) ----------------
__device__ float g_f[(size_t)NMAX * KPAD];   // concat(emb[idx], x_fixed), zero-padded
__device__ float g_W1[128 * KPAD];           // lin_W zero-padded to K=192
__device__ float g_h[(size_t)NMAX * DIM];    // hidden (ping)
__device__ float g_t[(size_t)NMAX * DIM];    // h @ W.T (pong)
__device__ float g_dinv[NMAX];
__device__ int   g_cnt[NMAX];
__device__ int   g_rowstart[NMAX + 1];
__device__ int   g_cursor[NMAX];
__device__ int   g_col[EMAX];
__device__ int   g_is64;

// packed fp32x2 FMA (sm_103a): d = a*b + c on 2 packed floats
#define FMA2(d, a, b) \
    asm("fma.rn.f32x2 %0, %1, %2, %0;" : "+l"(d) : "l"(a), "l"(b))
#define UNPACK2(lo, hi, v) \
    asm("mov.b64 {%0, %1}, %2;" : "=r"(lo), "=r"(hi) : "l"(v))

// ---------------- edge dtype detection ----------------
__global__ void detect_kernel(const int* __restrict__ w) {
    if (threadIdx.x == 0 && blockIdx.x == 0) {
        int any = 0;
        for (int i = 1; i < 256; i += 2) any |= w[i];
        g_is64 = (any == 0) ? 1 : 0;   // int64 little-endian: high words all zero
    }
}

__device__ __forceinline__ int load_edge(const void* edge, size_t pos, int is64) {
    if (is64) return (int)((const long long*)edge)[pos];
    return ((const int*)edge)[pos];
}

// ---------------- front-end: argmax + embedding + concat (+ cnt zeroing) ----------------
__global__ void prep_kernel(const float* __restrict__ x, const float* __restrict__ emb, int n) {
    int gw   = (blockIdx.x * blockDim.x + threadIdx.x) >> 5;
    int lane = threadIdx.x & 31;
    if (gw >= n) return;
    if (lane == 0) g_cnt[gw] = 0;
    const float* xi = x + (size_t)gw * 78;
    float best = -1e38f; int bi = 1 << 30;
    for (int k = lane; k < 44; k += 32) {
        float v = xi[k];
        if (v > best || (v == best && k < bi)) { best = v; bi = k; }
    }
    for (int off = 16; off; off >>= 1) {
        float ov = __shfl_xor_sync(0xffffffffu, best, off);
        int   oi = __shfl_xor_sync(0xffffffffu, bi, off);
        if (ov > best || (ov == best && oi < bi)) { best = ov; bi = oi; }
    }
    float* fi = g_f + (size_t)gw * KPAD;
    const float* er = emb + (size_t)bi * DIM;
    for (int k = lane; k < DIM; k += 32) fi[k] = er[k];
    for (int k = lane; k < 34;  k += 32) fi[DIM + k] = xi[44 + k];
    if (lane < 30) fi[162 + lane] = 0.f;   // zero pad 162..191
}

__global__ void padW_kernel(const float* __restrict__ W, float* __restrict__ Wp) {
    int idx = blockIdx.x * blockDim.x + threadIdx.x;
    if (idx >= 128 * KPAD) return;
    int o = idx / KPAD, k = idx - o * KPAD;
    Wp[idx] = (k < 162) ? W[o * 162 + k] : 0.f;
}

// ---------------- CSR build ----------------
__global__ void count_kernel(const void* __restrict__ edge, int e) {
    int i = blockIdx.x * blockDim.x + threadIdx.x;
    if (i >= e) return;
    int d = load_edge(edge, (size_t)e + i, g_is64);
    atomicAdd(&g_cnt[d], 1);
}

__global__ void scan_kernel(int n) {
    __shared__ int wsum[32];
    __shared__ int carry;
    int tid = threadIdx.x, lane = tid & 31, wid = tid >> 5;
    if (tid == 0) carry = 0;
    __syncthreads();
    for (int base = 0; base < n; base += 1024) {
        int i = base + tid;
        int v = (i < n) ? g_cnt[i] : 0;
        int x = v;
        #pragma unroll
        for (int off = 1; off < 32; off <<= 1) {
            int t = __shfl_up_sync(0xffffffffu, x, off);
            if (lane >= off) x += t;
        }
        if (lane == 31) wsum[wid] = x;
        __syncthreads();
        if (wid == 0) {
            int y = wsum[lane];
            #pragma unroll
            for (int off = 1; off < 32; off <<= 1) {
                int t = __shfl_up_sync(0xffffffffu, y, off);
                if (lane >= off) y += t;
            }
            wsum[lane] = y;
        }
        __syncthreads();
        int incl  = x + (wid ? wsum[wid - 1] : 0);
        int start = carry + incl - v;
        if (i < n) {
            g_rowstart[i] = start;
            g_cursor[i]   = start;
            g_dinv[i]     = rsqrtf((float)(v + 1));   // +1 self loop
        }
        int total = wsum[31];
        __syncthreads();
        if (tid == 0) carry += total;
        __syncthreads();
    }
    if (threadIdx.x == 0) g_rowstart[n] = carry;
}

__global__ void fill_kernel(const void* __restrict__ edge, int e) {
    int i = blockIdx.x * blockDim.x + threadIdx.x;
    if (i >= e) return;
    int is64 = g_is64;
    int s = load_edge(edge, (size_t)i, is64);
    int d = load_edge(edge, (size_t)e + i, is64);
    int p = atomicAdd(&g_cursor[d], 1);
    g_col[p] = s;
}

// ---------------- packed-f32x2 GEMM: C[n,128] = act(A[n,K] @ W[128,K]^T + b) ----------------
// 128 threads/block, tile = 64 nodes x 128 outs, 8x8 per thread, K chunked by 32.
// F staged k-major (LDS.128 = 4 nodes = 2 packed pairs), W staged as duplicated (w,w) pairs.
template<int K, bool RELU_BIAS>
__global__ void __launch_bounds__(128) gemm2_kernel(
    const float* __restrict__ A, const float* __restrict__ W,
    const float* __restrict__ bias, float* __restrict__ C, int n)
{
    __shared__ float2 Wd[32][130];   // [k][out] duplicated pairs, pad 2
    __shared__ float  Fs[32][68];    // [k][node], pad 4

    const int tid  = threadIdx.x;
    const int base = blockIdx.x * 64;
    const int tx   = tid & 15;   // out group: outs tx*8..tx*8+7
    const int ty   = tid >> 4;   // node group: nodes ty*8..ty*8+7

    unsigned long long acc[8][4];   // [jo][node-pair]
    #pragma unroll
    for (int a = 0; a < 8; a++)
        #pragma unroll
        for (int p = 0; p < 4; p++) acc[a][p] = 0ull;

    for (int k0 = 0; k0 < K; k0 += 32) {
        __syncthreads();
        // stage W chunk: 128 outs x 32 k, duplicated into pairs
        #pragma unroll
        for (int r = 0; r < 32; r++) {
            int idx = tid + r * 128;            // 4096
            int o = idx >> 5, kk = idx & 31;
            float v = W[o * K + k0 + kk];
            Wd[kk][o] = make_float2(v, v);
        }
        // stage F chunk: 64 nodes x 32 k (k-major in smem)
        #pragma unroll
        for (int r = 0; r < 16; r++) {
            int idx = tid + r * 128;            // 2048
            int node = idx >> 5, kk = idx & 31;
            int gi = base + node;
            Fs[kk][node] = (gi < n) ? A[(size_t)gi * K + k0 + kk] : 0.f;
        }
        __syncthreads();

        #pragma unroll
        for (int kk = 0; kk < 32; kk++) {
            const ulonglong2* wp = (const ulonglong2*)&Wd[kk][tx * 8];
            ulonglong2 wv0 = wp[0], wv1 = wp[1], wv2 = wp[2], wv3 = wp[3];
            unsigned long long w8[8] = {wv0.x, wv0.y, wv1.x, wv1.y,
                                        wv2.x, wv2.y, wv3.x, wv3.y};
            const ulonglong2* fp = (const ulonglong2*)&Fs[kk][ty * 8];
            ulonglong2 fv0 = fp[0], fv1 = fp[1];
            unsigned long long f4[4] = {fv0.x, fv0.y, fv1.x, fv1.y};
            #pragma unroll
            for (int jo = 0; jo < 8; jo++)
                #pragma unroll
                for (int p = 0; p < 4; p++)
                    FMA2(acc[jo][p], w8[jo], f4[p]);
        }
    }

    float bv[8];
    if (RELU_BIAS) {
        #pragma unroll
        for (int j = 0; j < 8; j++) bv[j] = bias[tx * 8 + j];
    }
    #pragma unroll
    for (int p = 0; p < 4; p++) {
        float v[2][8];
        #pragma unroll
        for (int jo = 0; jo < 8; jo++) {
            unsigned lo, hi;
            UNPACK2(lo, hi, acc[jo][p]);
            float flo = __uint_as_float(lo), fhi = __uint_as_float(hi);
            if (RELU_BIAS) {
                flo = fmaxf(flo + bv[jo], 0.f);
                fhi = fmaxf(fhi + bv[jo], 0.f);
            }
            v[0][jo] = flo; v[1][jo] = fhi;
        }
        #pragma unroll
        for (int h = 0; h < 2; h++) {
            int gi = base + ty * 8 + 2 * p + h;
            if (gi < n) {
                float* cp = C + (size_t)gi * 128 + tx * 8;
                *(float4*)cp       = make_float4(v[h][0], v[h][1], v[h][2], v[h][3]);
                *(float4*)(cp + 4) = make_float4(v[h][4], v[h][5], v[h][6], v[h][7]);
            }
        }
    }
}

// ---------------- CSR gather aggregation: out = relu(dinv_i*sum + dinv_i^2*t_i + b) ----------------
__global__ void agg_kernel(const float* __restrict__ t, const float* __restrict__ bias,
                           float* __restrict__ out, int n)
{
    int gw   = (blockIdx.x * blockDim.x + threadIdx.x) >> 5;
    int lane = threadIdx.x & 31;
    if (gw >= n) return;
    int r0 = g_rowstart[gw], r1 = g_rowstart[gw + 1];
    const float4* t4 = (const float4*)t;

    float4 a0 = make_float4(0.f, 0.f, 0.f, 0.f);
    float4 a1 = make_float4(0.f, 0.f, 0.f, 0.f);
    int e = r0;
    for (; e + 1 < r1; e += 2) {
        int s0 = g_col[e], s1 = g_col[e + 1];
        float w0 = g_dinv[s0], w1 = g_dinv[s1];
        float4 v0 = t4[(size_t)s0 * 32 + lane];
        float4 v1 = t4[(size_t)s1 * 32 + lane];
        a0.x = fmaf(w0, v0.x, a0.x); a0.y = fmaf(w0, v0.y, a0.y);
        a0.z = fmaf(w0, v0.z, a0.z); a0.w = fmaf(w0, v0.w, a0.w);
        a1.x = fmaf(w1, v1.x, a1.x); a1.y = fmaf(w1, v1.y, a1.y);
        a1.z = fmaf(w1, v1.z, a1.z); a1.w = fmaf(w1, v1.w, a1.w);
    }
    if (e < r1) {
        int s = g_col[e];
        float w = g_dinv[s];
        float4 v = t4[(size_t)s * 32 + lane];
        a0.x = fmaf(w, v.x, a0.x); a0.y = fmaf(w, v.y, a0.y);
        a0.z = fmaf(w, v.z, a0.z); a0.w = fmaf(w, v.w, a0.w);
    }
    float di  = g_dinv[gw];
    float di2 = di * di;
    float4 sv = t4[(size_t)gw * 32 + lane];
    float4 b4 = ((const float4*)bias)[lane];
    float4 o;
    o.x = fmaxf(di * (a0.x + a1.x) + di2 * sv.x + b4.x, 0.f);
    o.y = fmaxf(di * (a0.y + a1.y) + di2 * sv.y + b4.y, 0.f);
    o.z = fmaxf(di * (a0.z + a1.z) + di2 * sv.z + b4.z, 0.f);
    o.w = fmaxf(di * (a0.w + a1.w) + di2 * sv.w + b4.w, 0.f);
    ((float4*)out)[(size_t)gw * 32 + lane] = o;
}

// ---------------- launch ----------------
extern "C" void kernel_launch(void* const* d_in, const int* in_sizes, int n_in,
                              void* d_out, int out_size)
{
    const float* x     = (const float*)d_in[0];
    const void*  edge  = d_in[1];                 // int32 or int64, detected on device
    const float* emb   = (const float*)d_in[3];
    const float* lin_W = (const float*)d_in[4];
    const float* lin_b = (const float*)d_in[5];
    const float* g1W   = (const float*)d_in[6];
    const float* g1b   = (const float*)d_in[7];
    const float* g2W   = (const float*)d_in[8];
    const float* g2b   = (const float*)d_in[9];

    int n = in_sizes[0] / 78;
    int e = in_sizes[1] / 2;
    float* out = (float*)d_out;

    float *f_, *h_, *t_, *w1_;
    cudaGetSymbolAddress((void**)&f_, g_f);
    cudaGetSymbolAddress((void**)&h_, g_h);
    cudaGetSymbolAddress((void**)&t_, g_t);
    cudaGetSymbolAddress((void**)&w1_, g_W1);

    int ngrid_warp = (n + 7) / 8;         // 256 threads = 8 warps/block
    int egrid      = (e + 255) / 256;
    int gemm_grid  = (n + 63) / 64;

    detect_kernel<<<1, 32>>>((const int*)edge);
    prep_kernel<<<ngrid_warp, 256>>>(x, emb, n);
    padW_kernel<<<(128 * KPAD + 255) / 256, 256>>>(lin_W, w1_);
    count_kernel<<<egrid, 256>>>(edge, e);
    scan_kernel<<<1, 1024>>>(n);
    fill_kernel<<<egrid, 256>>>(edge, e);

    // h = relu(F @ lin_W^T + lin_b)
    gemm2_kernel<KPAD, true ><<<gemm_grid, 128>>>(f_, w1_, lin_b, h_, n);
    // layer 1
    gemm2_kernel<DIM, false><<<gemm_grid, 128>>>(h_, g1W, nullptr, t_, n);
    agg_kernel<<<ngrid_warp, 256>>>(t_, g1b, h_, n);
    // layer 2
    gemm2_kernel<DIM, false><<<gemm_grid, 128>>>(h_, g2W, nullptr, t_, n);
    agg_kernel<<<ngrid_warp, 256>>>(t_, g2b, out, n);
}

// round 6
// speedup vs baseline: 1.9341x; 1.9341x over previous
#include <cuda_runtime.h>
#include <cstdint>
#include <math.h>

#define NMAX 50000
#define EMAX 800000
#define DIM 128

// ---------------- scratch (device globals; no allocation allowed) ----------------
__device__ float g_h[(size_t)NMAX * DIM];
__device__ float g_t[(size_t)NMAX * DIM];
__device__ float g_embW[44 * DIM];   // emb @ lin_W[:, :128]^T
__device__ int   g_idx[NMAX];
__device__ float g_dinv[NMAX];
__device__ int   g_cnt[NMAX];
__device__ int   g_rowstart[NMAX + 1];
__device__ int   g_cursor[NMAX];
__device__ int   g_col[EMAX];
__device__ int   g_is64;

// packed fp32x2 FMA (sm_103): d = a*b + d on 2 packed floats
#define FMA2(d, a, b) \
    asm("fma.rn.f32x2 %0, %1, %2, %0;" : "+l"(d) : "l"(a), "l"(b))
#define UNPACK2(lo, hi, v) \
    asm("mov.b64 {%0, %1}, %2;" : "=r"(lo), "=r"(hi) : "l"(v))

// ---------------- edge dtype detection ----------------
__global__ void detect_kernel(const int* __restrict__ w) {
    if (threadIdx.x == 0 && blockIdx.x == 0) {
        int any = 0;
        for (int i = 1; i < 256; i += 2) any |= w[i];
        g_is64 = (any == 0) ? 1 : 0;   // int64 little-endian: high words all zero
    }
}
__device__ __forceinline__ int load_edge(const void* edge, size_t pos, int is64) {
    if (is64) return (int)((const long long*)edge)[pos];
    return ((const int*)edge)[pos];
}

// ---------------- prep: argmax over one-hot block -> g_idx (+ cnt zeroing) ----------------
__global__ void prep_kernel(const float* __restrict__ x, int n) {
    int gw   = (blockIdx.x * blockDim.x + threadIdx.x) >> 5;
    int lane = threadIdx.x & 31;
    if (gw >= n) return;
    if (lane == 0) g_cnt[gw] = 0;
    const float* xi = x + (size_t)gw * 78;
    float best = -1e38f; int bi = 1 << 30;
    for (int k = lane; k < 44; k += 32) {
        float v = xi[k];
        if (v > best || (v == best && k < bi)) { best = v; bi = k; }
    }
    for (int off = 16; off; off >>= 1) {
        float ov = __shfl_xor_sync(0xffffffffu, best, off);
        int   oi = __shfl_xor_sync(0xffffffffu, bi, off);
        if (ov > best || (ov == best && oi < bi)) { best = ov; bi = oi; }
    }
    if (lane == 0) g_idx[gw] = bi;
}

// ---------------- embW table: embW[r][o] = sum_k emb[r][k] * lin_W[o][k], k<128 ----------------
__global__ void embW_kernel(const float* __restrict__ emb, const float* __restrict__ linW) {
    int r = blockIdx.x;      // 0..43
    int o = threadIdx.x;     // 0..127
    const float* e = emb + r * 128;
    const float* w = linW + (size_t)o * 162;
    float acc = 0.f;
    #pragma unroll 8
    for (int k = 0; k < 128; k++) acc = fmaf(e[k], w[k], acc);
    g_embW[r * 128 + o] = acc;
}

// ---------------- CSR build ----------------
__global__ void count_kernel(const void* __restrict__ edge, int e) {
    int i = blockIdx.x * blockDim.x + threadIdx.x;
    if (i >= e) return;
    int d = load_edge(edge, (size_t)e + i, g_is64);
    atomicAdd(&g_cnt[d], 1);
}

__global__ void scan_kernel(int n) {
    __shared__ int wsum[32];
    __shared__ int carry;
    int tid = threadIdx.x, lane = tid & 31, wid = tid >> 5;
    if (tid == 0) carry = 0;
    __syncthreads();
    for (int base = 0; base < n; base += 1024) {
        int i = base + tid;
        int v = (i < n) ? g_cnt[i] : 0;
        int x = v;
        #pragma unroll
        for (int off = 1; off < 32; off <<= 1) {
            int t = __shfl_up_sync(0xffffffffu, x, off);
            if (lane >= off) x += t;
        }
        if (lane == 31) wsum[wid] = x;
        __syncthreads();
        if (wid == 0) {
            int y = wsum[lane];
            #pragma unroll
            for (int off = 1; off < 32; off <<= 1) {
                int t = __shfl_up_sync(0xffffffffu, y, off);
                if (lane >= off) y += t;
            }
            wsum[lane] = y;
        }
        __syncthreads();
        int incl  = x + (wid ? wsum[wid - 1] : 0);
        int start = carry + incl - v;
        if (i < n) {
            g_rowstart[i] = start;
            g_cursor[i]   = start;
            g_dinv[i]     = rsqrtf((float)(v + 1));   // +1 self loop
        }
        int total = wsum[31];
        __syncthreads();
        if (tid == 0) carry += total;
        __syncthreads();
    }
    if (threadIdx.x == 0) g_rowstart[n] = carry;
}

__global__ void fill_kernel(const void* __restrict__ edge, int e) {
    int i = blockIdx.x * blockDim.x + threadIdx.x;
    if (i >= e) return;
    int is64 = g_is64;
    int s = load_edge(edge, (size_t)i, is64);
    int d = load_edge(edge, (size_t)e + i, is64);
    int p = atomicAdd(&g_cursor[d], 1);
    g_col[p] = s;
}

// ---------------- front: h = relu(embW[idx] + xfix @ Wfix^T + b), K=34 via f32x2 ----------------
// 1024 threads = 32 warps = 32 nodes per CTA; warp per node, lane handles outs l,l+32,l+64,l+96.
__global__ void __launch_bounds__(1024) front_kernel(
    const float* __restrict__ x, const float* __restrict__ linW,
    const float* __restrict__ linb, int n)
{
    __shared__ float Wf[128 * 34];   // Wfix[o][k] = lin_W[o][128+k], pitch 34 (conflict-free)
    __shared__ float sxf[32 * 34];   // xfix per node
    const int tid  = threadIdx.x;
    const int base = blockIdx.x * 32;

    for (int idx = tid; idx < 128 * 34; idx += 1024) {
        int o = idx / 34, k = idx - o * 34;
        Wf[idx] = linW[(size_t)o * 162 + 128 + k];
    }
    for (int idx = tid; idx < 32 * 34; idx += 1024) {
        int nd = idx / 34, k = idx - nd * 34;
        int gi = base + nd;
        sxf[idx] = (gi < n) ? x[(size_t)gi * 78 + 44 + k] : 0.f;
    }
    __syncthreads();

    const int w = tid >> 5, l = tid & 31;
    const int gi = base + w;
    if (gi >= n) return;

    unsigned long long acc[4] = {0ull, 0ull, 0ull, 0ull};
    const unsigned long long* xp = (const unsigned long long*)(sxf + w * 34);
    #pragma unroll
    for (int kp = 0; kp < 17; kp++) {
        unsigned long long f2 = xp[kp];   // broadcast
        #pragma unroll
        for (int q = 0; q < 4; q++) {
            unsigned long long w2 = *(const unsigned long long*)(Wf + (l + 32 * q) * 34 + 2 * kp);
            FMA2(acc[q], w2, f2);
        }
    }
    const float* er = g_embW + g_idx[gi] * 128;
    #pragma unroll
    for (int q = 0; q < 4; q++) {
        int o = l + 32 * q;
        unsigned lo, hi; UNPACK2(lo, hi, acc[q]);
        float v = __uint_as_float(lo) + __uint_as_float(hi) + er[o] + linb[o];
        g_h[(size_t)gi * 128 + o] = fmaxf(v, 0.f);
    }
}

// ---------------- square GEMM: out[n,128] = A[n,128] @ W[128,128]^T, f32x2 K-packed ----------------
// 256 threads, tile 64 nodes x 128 outs. tx=tid&15 -> outs {tx+16j}, ty=tid>>4 -> nodes {ty*4+m}.
// Smem layout: row-pitch 128 floats, float4 slot swizzle q^=(row&15) -> all LDS/STS conflict-free.
__global__ void __launch_bounds__(256) gemm2_kernel(
    const float* __restrict__ A, const float* __restrict__ W,
    float* __restrict__ out, int n)
{
    extern __shared__ float sm[];
    float* Ws = sm;              // 128 x 128
    float* Fs = sm + 128 * 128;  // 64 x 128
    const int tid  = threadIdx.x;
    const int base = blockIdx.x * 64;

    #pragma unroll
    for (int i = 0; i < 16; i++) {           // W: 4096 float4
        int idx = tid + i * 256;
        int o = idx >> 5, q = idx & 31;
        float4 v = *(const float4*)(W + (size_t)o * 128 + q * 4);
        *(float4*)(Ws + o * 128 + (q ^ (o & 15)) * 4) = v;
    }
    #pragma unroll
    for (int i = 0; i < 8; i++) {            // F: 2048 float4 (zero-fill tail)
        int idx = tid + i * 256;
        int nd = idx >> 5, q = idx & 31;
        int gi = base + nd;
        float4 v = (gi < n) ? *(const float4*)(A + (size_t)gi * 128 + q * 4)
                            : make_float4(0.f, 0.f, 0.f, 0.f);
        *(float4*)(Fs + nd * 128 + (q ^ (nd & 15)) * 4) = v;
    }
    __syncthreads();

    const int tx = tid & 15, ty = tid >> 4;
    unsigned long long acc[8][4];
    #pragma unroll
    for (int j = 0; j < 8; j++)
        #pragma unroll
        for (int m = 0; m < 4; m++) acc[j][m] = 0ull;

    #pragma unroll 8
    for (int kq = 0; kq < 32; kq++) {        // each kq = 1 float4 = 2 packed k-pairs
        ulonglong2 wv[8];
        #pragma unroll
        for (int j = 0; j < 8; j++)
            wv[j] = *(const ulonglong2*)(Ws + (tx + 16 * j) * 128 + ((kq ^ tx) * 4));
        ulonglong2 fv[4];
        #pragma unroll
        for (int m = 0; m < 4; m++) {
            int nd = ty * 4 + m;
            fv[m] = *(const ulonglong2*)(Fs + nd * 128 + ((kq ^ (nd & 15)) * 4));
        }
        #pragma unroll
        for (int j = 0; j < 8; j++)
            #pragma unroll
            for (int m = 0; m < 4; m++) {
                FMA2(acc[j][m], wv[j].x, fv[m].x);
                FMA2(acc[j][m], wv[j].y, fv[m].y);
            }
    }

    #pragma unroll
    for (int m = 0; m < 4; m++) {
        int gi = base + ty * 4 + m;
        if (gi < n) {
            #pragma unroll
            for (int j = 0; j < 8; j++) {
                unsigned lo, hi; UNPACK2(lo, hi, acc[j][m]);
                out[(size_t)gi * 128 + tx + 16 * j] = __uint_as_float(lo) + __uint_as_float(hi);
            }
        }
    }
}

// ---------------- CSR gather aggregation: o = relu(dinv_i*sum + dinv_i^2*t_i + b) ----------------
__global__ void agg_kernel(const float* __restrict__ t, const float* __restrict__ bias,
                           float* __restrict__ out, int n)
{
    int gw   = (blockIdx.x * blockDim.x + threadIdx.x) >> 5;
    int lane = threadIdx.x & 31;
    if (gw >= n) return;
    int r0 = g_rowstart[gw], r1 = g_rowstart[gw + 1];
    const float4* t4 = (const float4*)t;

    float4 a0 = make_float4(0.f, 0.f, 0.f, 0.f);
    float4 a1 = make_float4(0.f, 0.f, 0.f, 0.f);
    int e = r0;
    for (; e + 1 < r1; e += 2) {
        int s0 = g_col[e], s1 = g_col[e + 1];
        float w0 = g_dinv[s0], w1 = g_dinv[s1];
        float4 v0 = t4[(size_t)s0 * 32 + lane];
        float4 v1 = t4[(size_t)s1 * 32 + lane];
        a0.x = fmaf(w0, v0.x, a0.x); a0.y = fmaf(w0, v0.y, a0.y);
        a0.z = fmaf(w0, v0.z, a0.z); a0.w = fmaf(w0, v0.w, a0.w);
        a1.x = fmaf(w1, v1.x, a1.x); a1.y = fmaf(w1, v1.y, a1.y);
        a1.z = fmaf(w1, v1.z, a1.z); a1.w = fmaf(w1, v1.w, a1.w);
    }
    if (e < r1) {
        int s = g_col[e];
        float w = g_dinv[s];
        float4 v = t4[(size_t)s * 32 + lane];
        a0.x = fmaf(w, v.x, a0.x); a0.y = fmaf(w, v.y, a0.y);
        a0.z = fmaf(w, v.z, a0.z); a0.w = fmaf(w, v.w, a0.w);
    }
    float di  = g_dinv[gw];
    float di2 = di * di;
    float4 sv = t4[(size_t)gw * 32 + lane];
    float4 b4 = ((const float4*)bias)[lane];
    float4 o;
    o.x = fmaxf(di * (a0.x + a1.x) + di2 * sv.x + b4.x, 0.f);
    o.y = fmaxf(di * (a0.y + a1.y) + di2 * sv.y + b4.y, 0.f);
    o.z = fmaxf(di * (a0.z + a1.z) + di2 * sv.z + b4.z, 0.f);
    o.w = fmaxf(di * (a0.w + a1.w) + di2 * sv.w + b4.w, 0.f);
    ((float4*)out)[(size_t)gw * 32 + lane] = o;
}

// ---------------- launch ----------------
extern "C" void kernel_launch(void* const* d_in, const int* in_sizes, int n_in,
                              void* d_out, int out_size)
{
    const float* x     = (const float*)d_in[0];
    const void*  edge  = d_in[1];
    const float* emb   = (const float*)d_in[3];
    const float* lin_W = (const float*)d_in[4];
    const float* lin_b = (const float*)d_in[5];
    const float* g1W   = (const float*)d_in[6];
    const float* g1b   = (const float*)d_in[7];
    const float* g2W   = (const float*)d_in[8];
    const float* g2b   = (const float*)d_in[9];

    int n = in_sizes[0] / 78;
    int e = in_sizes[1] / 2;
    float* out = (float*)d_out;

    float *h_, *t_;
    cudaGetSymbolAddress((void**)&h_, g_h);
    cudaGetSymbolAddress((void**)&t_, g_t);

    const int GSMEM = (128 * 128 + 64 * 128) * 4;   // 98304
    cudaFuncSetAttribute(gemm2_kernel, cudaFuncAttributeMaxDynamicSharedMemorySize, GSMEM);

    int ngrid_warp = (n + 7) / 8;
    int egrid      = (e + 255) / 256;
    int ggrid      = (n + 63) / 64;
    int fgrid      = (n + 31) / 32;

    detect_kernel<<<1, 32>>>((const int*)edge);
    prep_kernel<<<ngrid_warp, 256>>>(x, n);
    embW_kernel<<<44, 128>>>(emb, lin_W);
    count_kernel<<<egrid, 256>>>(edge, e);
    scan_kernel<<<1, 1024>>>(n);
    fill_kernel<<<egrid, 256>>>(edge, e);

    // h = relu(embW[idx] + xfix @ Wfix^T + lin_b)
    front_kernel<<<fgrid, 1024>>>(x, lin_W, lin_b, n);
    // layer 1
    gemm2_kernel<<<ggrid, 256, GSMEM>>>(h_, g1W, t_, n);
    agg_kernel<<<ngrid_warp, 256>>>(t_, g1b, h_, n);
    // layer 2
    gemm2_kernel<<<ggrid, 256, GSMEM>>>(h_, g2W, t_, n);
    agg_kernel<<<ngrid_warp, 256>>>(t_, g2b, out, n);
}

// round 7
// speedup vs baseline: 2.2484x; 1.1625x over previous
#include <cuda_runtime.h>
#include <cstdint>
#include <math.h>

#define NMAX 50000
#define EMAX 800000
#define DIM 128
#define SCB 256          // scan block size

// ---------------- scratch (device globals; no allocation allowed) ----------------
__device__ float g_h[(size_t)NMAX * DIM];
__device__ float g_t[(size_t)NMAX * DIM];
__device__ float g_embW[44 * DIM];   // emb @ lin_W[:, :128]^T
__device__ int   g_idx[NMAX];
__device__ float g_dinv[NMAX];
__device__ int   g_cnt[NMAX];
__device__ int   g_rowstart[NMAX + 1];
__device__ int   g_cursor[NMAX];
__device__ int   g_col[EMAX];
__device__ int   g_part[1024];       // per-block partial sums
__device__ int   g_pscan[1024];      // exclusive scan of partials
__device__ int   g_is64;

// packed fp32x2 FMA (sm_103): d = a*b + d on 2 packed floats
#define FMA2(d, a, b) \
    asm("fma.rn.f32x2 %0, %1, %2, %0;" : "+l"(d) : "l"(a), "l"(b))
#define UNPACK2(lo, hi, v) \
    asm("mov.b64 {%0, %1}, %2;" : "=r"(lo), "=r"(hi) : "l"(v))

__device__ __forceinline__ int load_edge(const void* edge, size_t pos, int is64) {
    if (is64) return (int)((const long long*)edge)[pos];
    return ((const int*)edge)[pos];
}

// ---------------- prep: argmax -> g_idx, cnt zeroing, + edge dtype detect ----------------
__global__ void prep_kernel(const float* __restrict__ x, const int* __restrict__ ew, int n) {
    if (blockIdx.x == 0 && threadIdx.x == 0) {
        int any = 0;
        for (int i = 1; i < 256; i += 2) any |= ew[i];
        g_is64 = (any == 0) ? 1 : 0;   // int64 little-endian: high words all zero
    }
    int gw   = (blockIdx.x * blockDim.x + threadIdx.x) >> 5;
    int lane = threadIdx.x & 31;
    if (gw >= n) return;
    if (lane == 0) g_cnt[gw] = 0;
    const float* xi = x + (size_t)gw * 78;
    float best = -1e38f; int bi = 1 << 30;
    for (int k = lane; k < 44; k += 32) {
        float v = xi[k];
        if (v > best || (v == best && k < bi)) { best = v; bi = k; }
    }
    for (int off = 16; off; off >>= 1) {
        float ov = __shfl_xor_sync(0xffffffffu, best, off);
        int   oi = __shfl_xor_sync(0xffffffffu, bi, off);
        if (ov > best || (ov == best && oi < bi)) { best = ov; bi = oi; }
    }
    if (lane == 0) g_idx[gw] = bi;
}

// ---------------- embW table: embW[r][o] = sum_k emb[r][k] * lin_W[o][k], k<128 ----------------
__global__ void embW_kernel(const float* __restrict__ emb, const float* __restrict__ linW) {
    int r = blockIdx.x;      // 0..43
    int o = threadIdx.x;     // 0..127
    const float* e = emb + r * 128;
    const float* w = linW + (size_t)o * 162;
    float acc = 0.f;
    #pragma unroll 8
    for (int k = 0; k < 128; k++) acc = fmaf(e[k], w[k], acc);
    g_embW[r * 128 + o] = acc;
}

// ---------------- CSR build ----------------
__global__ void count_kernel(const void* __restrict__ edge, int e) {
    int i = blockIdx.x * blockDim.x + threadIdx.x;
    if (i >= e) return;
    int d = load_edge(edge, (size_t)e + i, g_is64);
    atomicAdd(&g_cnt[d], 1);
}

// phase 1: per-block (256 elems) reduce -> g_part[b]
__global__ void scan1_kernel(int n) {
    __shared__ int wsum[8];
    int i = blockIdx.x * SCB + threadIdx.x;
    int lane = threadIdx.x & 31, wid = threadIdx.x >> 5;
    int v = (i < n) ? g_cnt[i] : 0;
    for (int off = 16; off; off >>= 1) v += __shfl_xor_sync(0xffffffffu, v, off);
    if (lane == 0) wsum[wid] = v;
    __syncthreads();
    if (threadIdx.x == 0) {
        int s = 0;
        #pragma unroll
        for (int w = 0; w < 8; w++) s += wsum[w];
        g_part[blockIdx.x] = s;
    }
}

// phase 2: single block scans partials (nb <= 1024 handled with loop over 256-chunks)
__global__ void scan2_kernel(int nb, int n) {
    __shared__ int wsum[8];
    __shared__ int carry;
    int tid = threadIdx.x, lane = tid & 31, wid = tid >> 5;
    if (tid == 0) carry = 0;
    __syncthreads();
    for (int base = 0; base < nb; base += SCB) {
        int i = base + tid;
        int v = (i < nb) ? g_part[i] : 0;
        int x = v;
        #pragma unroll
        for (int off = 1; off < 32; off <<= 1) {
            int t = __shfl_up_sync(0xffffffffu, x, off);
            if (lane >= off) x += t;
        }
        if (lane == 31) wsum[wid] = x;
        __syncthreads();
        if (wid == 0 && lane < 8) {
            int y = wsum[lane];
            #pragma unroll
            for (int off = 1; off < 8; off <<= 1) {
                int t = __shfl_up_sync(0xffu, y, off);
                if (lane >= off) y += t;
            }
            wsum[lane] = y;
        }
        __syncthreads();
        int incl = x + (wid ? wsum[wid - 1] : 0) + carry;
        if (i < nb) g_pscan[i] = incl - v;   // exclusive
        int total = wsum[7];
        __syncthreads();
        if (tid == 0) carry += total;
        __syncthreads();
    }
    if (tid == 0) g_rowstart[n] = carry;
}

// phase 3: block scan + apply offset -> rowstart, cursor, dinv
__global__ void scan3_kernel(int n) {
    __shared__ int wsum[8];
    int i = blockIdx.x * SCB + threadIdx.x;
    int lane = threadIdx.x & 31, wid = threadIdx.x >> 5;
    int v = (i < n) ? g_cnt[i] : 0;
    int x = v;
    #pragma unroll
    for (int off = 1; off < 32; off <<= 1) {
        int t = __shfl_up_sync(0xffffffffu, x, off);
        if (lane >= off) x += t;
    }
    if (lane == 31) wsum[wid] = x;
    __syncthreads();
    if (wid == 0 && lane < 8) {
        int y = wsum[lane];
        #pragma unroll
        for (int off = 1; off < 8; off <<= 1) {
            int t = __shfl_up_sync(0xffu, y, off);
            if (lane >= off) y += t;
        }
        wsum[lane] = y;
    }
    __syncthreads();
    if (i < n) {
        int start = g_pscan[blockIdx.x] + x + (wid ? wsum[wid - 1] : 0) - v;
        g_rowstart[i] = start;
        g_cursor[i]   = start;
        g_dinv[i]     = rsqrtf((float)(v + 1));   // +1 self loop
    }
}

__global__ void fill_kernel(const void* __restrict__ edge, int e) {
    int i = blockIdx.x * blockDim.x + threadIdx.x;
    if (i >= e) return;
    int is64 = g_is64;
    int s = load_edge(edge, (size_t)i, is64);
    int d = load_edge(edge, (size_t)e + i, is64);
    int p = atomicAdd(&g_cursor[d], 1);
    g_col[p] = s;
}

// ---------------- front: h = relu(embW[idx] + xfix @ Wfix^T + b), K=34 via f32x2 ----------------
__global__ void __launch_bounds__(1024) front_kernel(
    const float* __restrict__ x, const float* __restrict__ linW,
    const float* __restrict__ linb, int n)
{
    __shared__ float Wf[128 * 34];   // Wfix[o][k] = lin_W[o][128+k], pitch 34
    __shared__ float sxf[32 * 34];   // xfix per node
    const int tid  = threadIdx.x;
    const int base = blockIdx.x * 32;

    for (int idx = tid; idx < 128 * 34; idx += 1024) {
        int o = idx / 34, k = idx - o * 34;
        Wf[idx] = linW[(size_t)o * 162 + 128 + k];
    }
    for (int idx = tid; idx < 32 * 34; idx += 1024) {
        int nd = idx / 34, k = idx - nd * 34;
        int gi = base + nd;
        sxf[idx] = (gi < n) ? x[(size_t)gi * 78 + 44 + k] : 0.f;
    }
    __syncthreads();

    const int w = tid >> 5, l = tid & 31;
    const int gi = base + w;
    if (gi >= n) return;

    unsigned long long acc[4] = {0ull, 0ull, 0ull, 0ull};
    const unsigned long long* xp = (const unsigned long long*)(sxf + w * 34);
    #pragma unroll
    for (int kp = 0; kp < 17; kp++) {
        unsigned long long f2 = xp[kp];
        #pragma unroll
        for (int q = 0; q < 4; q++) {
            unsigned long long w2 = *(const unsigned long long*)(Wf + (l + 32 * q) * 34 + 2 * kp);
            FMA2(acc[q], w2, f2);
        }
    }
    const float* er = g_embW + g_idx[gi] * 128;
    #pragma unroll
    for (int q = 0; q < 4; q++) {
        int o = l + 32 * q;
        unsigned lo, hi; UNPACK2(lo, hi, acc[q]);
        float v = __uint_as_float(lo) + __uint_as_float(hi) + er[o] + linb[o];
        g_h[(size_t)gi * 128 + o] = fmaxf(v, 0.f);
    }
}

// ---------------- square GEMM: out[n,128] = A[n,128] @ W[128,128]^T, f32x2 K-packed ----------------
__global__ void __launch_bounds__(256) gemm2_kernel(
    const float* __restrict__ A, const float* __restrict__ W,
    float* __restrict__ out, int n)
{
    extern __shared__ float sm[];
    float* Ws = sm;              // 128 x 128
    float* Fs = sm + 128 * 128;  // 64 x 128
    const int tid  = threadIdx.x;
    const int base = blockIdx.x * 64;

    #pragma unroll
    for (int i = 0; i < 16; i++) {
        int idx = tid + i * 256;
        int o = idx >> 5, q = idx & 31;
        float4 v = *(const float4*)(W + (size_t)o * 128 + q * 4);
        *(float4*)(Ws + o * 128 + (q ^ (o & 15)) * 4) = v;
    }
    #pragma unroll
    for (int i = 0; i < 8; i++) {
        int idx = tid + i * 256;
        int nd = idx >> 5, q = idx & 31;
        int gi = base + nd;
        float4 v = (gi < n) ? *(const float4*)(A + (size_t)gi * 128 + q * 4)
                            : make_float4(0.f, 0.f, 0.f, 0.f);
        *(float4*)(Fs + nd * 128 + (q ^ (nd & 15)) * 4) = v;
    }
    __syncthreads();

    const int tx = tid & 15, ty = tid >> 4;
    unsigned long long acc[8][4];
    #pragma unroll
    for (int j = 0; j < 8; j++)
        #pragma unroll
        for (int m = 0; m < 4; m++) acc[j][m] = 0ull;

    #pragma unroll 8
    for (int kq = 0; kq < 32; kq++) {
        ulonglong2 wv[8];
        #pragma unroll
        for (int j = 0; j < 8; j++)
            wv[j] = *(const ulonglong2*)(Ws + (tx + 16 * j) * 128 + ((kq ^ tx) * 4));
        ulonglong2 fv[4];
        #pragma unroll
        for (int m = 0; m < 4; m++) {
            int nd = ty * 4 + m;
            fv[m] = *(const ulonglong2*)(Fs + nd * 128 + ((kq ^ (nd & 15)) * 4));
        }
        #pragma unroll
        for (int j = 0; j < 8; j++)
            #pragma unroll
            for (int m = 0; m < 4; m++) {
                FMA2(acc[j][m], wv[j].x, fv[m].x);
                FMA2(acc[j][m], wv[j].y, fv[m].y);
            }
    }

    #pragma unroll
    for (int m = 0; m < 4; m++) {
        int gi = base + ty * 4 + m;
        if (gi < n) {
            #pragma unroll
            for (int j = 0; j < 8; j++) {
                unsigned lo, hi; UNPACK2(lo, hi, acc[j][m]);
                out[(size_t)gi * 128 + tx + 16 * j] = __uint_as_float(lo) + __uint_as_float(hi);
            }
        }
    }
}

// ---------------- CSR gather aggregation, 4-edge unrolled ----------------
__global__ void agg_kernel(const float* __restrict__ t, const float* __restrict__ bias,
                           float* __restrict__ out, int n)
{
    int gw   = (blockIdx.x * blockDim.x + threadIdx.x) >> 5;
    int lane = threadIdx.x & 31;
    if (gw >= n) return;
    int r0 = g_rowstart[gw], r1 = g_rowstart[gw + 1];
    const float4* t4 = (const float4*)t;

    float4 a0 = make_float4(0.f, 0.f, 0.f, 0.f);
    float4 a1 = make_float4(0.f, 0.f, 0.f, 0.f);
    int e = r0;
    for (; e + 3 < r1; e += 4) {
        int s0 = g_col[e],     s1 = g_col[e + 1];
        int s2 = g_col[e + 2], s3 = g_col[e + 3];
        float w0 = g_dinv[s0], w1 = g_dinv[s1], w2 = g_dinv[s2], w3 = g_dinv[s3];
        float4 v0 = t4[(size_t)s0 * 32 + lane];
        float4 v1 = t4[(size_t)s1 * 32 + lane];
        float4 v2 = t4[(size_t)s2 * 32 + lane];
        float4 v3 = t4[(size_t)s3 * 32 + lane];
        a0.x = fmaf(w0, v0.x, a0.x); a0.y = fmaf(w0, v0.y, a0.y);
        a0.z = fmaf(w0, v0.z, a0.z); a0.w = fmaf(w0, v0.w, a0.w);
        a1.x = fmaf(w1, v1.x, a1.x); a1.y = fmaf(w1, v1.y, a1.y);
        a1.z = fmaf(w1, v1.z, a1.z); a1.w = fmaf(w1, v1.w, a1.w);
        a0.x = fmaf(w2, v2.x, a0.x); a0.y = fmaf(w2, v2.y, a0.y);
        a0.z = fmaf(w2, v2.z, a0.z); a0.w = fmaf(w2, v2.w, a0.w);
        a1.x = fmaf(w3, v3.x, a1.x); a1.y = fmaf(w3, v3.y, a1.y);
        a1.z = fmaf(w3, v3.z, a1.z); a1.w = fmaf(w3, v3.w, a1.w);
    }
    for (; e < r1; e++) {
        int s = g_col[e];
        float w = g_dinv[s];
        float4 v = t4[(size_t)s * 32 + lane];
        a0.x = fmaf(w, v.x, a0.x); a0.y = fmaf(w, v.y, a0.y);
        a0.z = fmaf(w, v.z, a0.z); a0.w = fmaf(w, v.w, a0.w);
    }
    float di  = g_dinv[gw];
    float di2 = di * di;
    float4 sv = t4[(size_t)gw * 32 + lane];
    float4 b4 = ((const float4*)bias)[lane];
    float4 o;
    o.x = fmaxf(di * (a0.x + a1.x) + di2 * sv.x + b4.x, 0.f);
    o.y = fmaxf(di * (a0.y + a1.y) + di2 * sv.y + b4.y, 0.f);
    o.z = fmaxf(di * (a0.z + a1.z) + di2 * sv.z + b4.z, 0.f);
    o.w = fmaxf(di * (a0.w + a1.w) + di2 * sv.w + b4.w, 0.f);
    ((float4*)out)[(size_t)gw * 32 + lane] = o;
}

// ---------------- launch ----------------
extern "C" void kernel_launch(void* const* d_in, const int* in_sizes, int n_in,
                              void* d_out, int out_size)
{
    const float* x     = (const float*)d_in[0];
    const void*  edge  = d_in[1];
    const float* emb   = (const float*)d_in[3];
    const float* lin_W = (const float*)d_in[4];
    const float* lin_b = (const float*)d_in[5];
    const float* g1W   = (const float*)d_in[6];
    const float* g1b   = (const float*)d_in[7];
    const float* g2W   = (const float*)d_in[8];
    const float* g2b   = (const float*)d_in[9];

    int n = in_sizes[0] / 78;
    int e = in_sizes[1] / 2;
    float* out = (float*)d_out;

    float *h_, *t_;
    cudaGetSymbolAddress((void**)&h_, g_h);
    cudaGetSymbolAddress((void**)&t_, g_t);

    const int GSMEM = (128 * 128 + 64 * 128) * 4;   // 98304
    cudaFuncSetAttribute(gemm2_kernel, cudaFuncAttributeMaxDynamicSharedMemorySize, GSMEM);

    int ngrid_warp = (n + 7) / 8;
    int egrid      = (e + 255) / 256;
    int ggrid      = (n + 63) / 64;
    int fgrid      = (n + 31) / 32;
    int nb         = (n + SCB - 1) / SCB;

    prep_kernel<<<ngrid_warp, 256>>>(x, (const int*)edge, n);
    embW_kernel<<<44, 128>>>(emb, lin_W);
    count_kernel<<<egrid, 256>>>(edge, e);
    scan1_kernel<<<nb, SCB>>>(n);
    scan2_kernel<<<1, SCB>>>(nb, n);
    scan3_kernel<<<nb, SCB>>>(n);
    fill_kernel<<<egrid, 256>>>(edge, e);

    front_kernel<<<fgrid, 1024>>>(x, lin_W, lin_b, n);
    // layer 1
    gemm2_kernel<<<ggrid, 256, GSMEM>>>(h_, g1W, t_, n);
    agg_kernel<<<ngrid_warp, 256>>>(t_, g1b, h_, n);
    // layer 2
    gemm2_kernel<<<ggrid, 256, GSMEM>>>(h_, g2W, t_, n);
    agg_kernel<<<ngrid_warp, 256>>>(t_, g2b, out, n);
}